// round 1
// baseline (speedup 1.0000x reference)
#include <cuda_runtime.h>
#include <cstdint>

// Problem constants
#define BB 4096
#define SS 200
#define DD 64
#define HH 36
#define NROWS (BB*SS)          // 819200
#define ROWF  (SS*HH)          // 7200 floats of h per batch

// ---------------- device scratch (no allocations allowed) ----------------
__device__ float g_h[(size_t)NROWS * HH];     // 118 MB staged h
__device__ float g_part[BB * 72];             // per-block [sum(36), sumsq(36)]
__device__ float g_stats[72];                 // reduced sums

// packed fp32x2 FMA (FFMA2) — double-rate fp32 on sm_103a
__device__ __forceinline__ void ffma2(unsigned long long& d,
                                      unsigned long long a,
                                      unsigned long long b) {
    asm volatile("fma.rn.f32x2 %0, %1, %2, %0;" : "+l"(d) : "l"(a), "l"(b));
}

// ---------------- pass 1: per-batch GEMM h = hist @ M_b + u_b -------------
// grid = 4096 blocks (1 batch each), 192 threads.
// Dynamic SMEM layout:
//   [0,53248)      float2 histP[64][104]  : hist transposed+pair-packed, histP[k][p] = {h[2p][k], h[2p+1][k]}
//   [53248,71680)  float2 msp[64][36]     : splatted M, msp[k][j] = {M[k][j], M[k][j]}
//   [71680,71824)  float  u[36]
//   [71824,72080)  float  cbuf[64]
//   htile (float[200*37], 29600 B) aliases [0,29600) AFTER the GEMM k-loop.
#define SMEM1 72080

__global__ void __launch_bounds__(192)
pass1_kernel(const float* __restrict__ hist,
             const float* __restrict__ cand,
             const float* __restrict__ W1,
             const float* __restrict__ b1)
{
    extern __shared__ unsigned char smem_raw[];
    float*  hpF   = (float*)smem_raw;                         // view of histP (row stride 208 floats)
    float2* msp2  = (float2*)(smem_raw + 53248);
    const unsigned long long* mspU = (const unsigned long long*)(smem_raw + 53248);
    float*  u     = (float*)(smem_raw + 71680);
    float*  cbuf  = (float*)(smem_raw + 71824);
    float*  htile = (float*)smem_raw;                         // alias, valid after sync

    const int tid = threadIdx.x;
    const int b   = blockIdx.x;
    const float* hb = hist + (size_t)b * (SS * DD);

    // stage candidate
    if (tid < 64) cbuf[tid] = cand[b * 64 + tid];
    __syncthreads();

    // build M splat pairs: M[k][j] = W1[64+k][j] - W1[128+k][j] + cand[k]*W1[192+k][j]
    for (int e = tid; e < 64 * 36; e += 192) {
        int k = e / 36;
        int j = e - k * 36;
        float m = W1[(64 + k) * 36 + j] - W1[(128 + k) * 36 + j]
                + cbuf[k] * W1[(192 + k) * 36 + j];
        msp2[e] = make_float2(m, m);
    }
    // build u[j] = b1[j] + sum_k cand[k]*(W1[k][j] + W1[128+k][j])
    if (tid < 36) {
        int j = tid;
        float a = b1[j];
        #pragma unroll 8
        for (int k = 0; k < 64; k++)
            a += cbuf[k] * (W1[k * 36 + j] + W1[(128 + k) * 36 + j]);
        u[j] = a;
    }
    // load hist tile, transposed & pair-packed: hpF[d*208 + s]
    {
        const float4* h4 = (const float4*)hb;     // 200*64/4 = 3200 float4
        for (int f = tid; f < 3200; f += 192) {
            float4 v = h4[f];
            int s  = f >> 4;
            int d4 = (f & 15) << 2;
            hpF[(d4 + 0) * 208 + s] = v.x;
            hpF[(d4 + 1) * 208 + s] = v.y;
            hpF[(d4 + 2) * 208 + s] = v.z;
            hpF[(d4 + 3) * 208 + s] = v.w;
        }
    }
    __syncthreads();

    // ---- GEMM: warp w owns cols [6w,6w+6), lane l (<25) owns rows [8l,8l+8) ----
    const int w  = tid >> 5;          // 0..5
    const int l  = tid & 31;          // 0..31 (25 active)
    const int jc = w * 6;
    const bool act = (l < 25);

    unsigned long long acc[4][6];
    #pragma unroll
    for (int r = 0; r < 4; r++)
        #pragma unroll
        for (int jj = 0; jj < 6; jj++) acc[r][jj] = 0ull;

    if (act) {
        const unsigned long long* hpU = (const unsigned long long*)smem_raw; // pair index
        #pragma unroll 2
        for (int k = 0; k < 64; k++) {
            const unsigned long long* hrow = hpU + k * 104 + 4 * l;
            ulonglong2 A0 = *(const ulonglong2*)(hrow);
            ulonglong2 A1 = *(const ulonglong2*)(hrow + 2);
            unsigned long long hr0 = A0.x, hr1 = A0.y, hr2 = A1.x, hr3 = A1.y;
            #pragma unroll
            for (int jj = 0; jj < 6; jj++) {
                unsigned long long m = mspU[k * 36 + jc + jj];
                ffma2(acc[0][jj], hr0, m);
                ffma2(acc[1][jj], hr1, m);
                ffma2(acc[2][jj], hr2, m);
                ffma2(acc[3][jj], hr3, m);
            }
        }
    }

    // ---- per-thread stats, then warp reduce (deterministic partials) ----
    float sum6[6], sq6[6];
    #pragma unroll
    for (int jj = 0; jj < 6; jj++) { sum6[jj] = 0.f; sq6[jj] = 0.f; }
    if (act) {
        #pragma unroll
        for (int jj = 0; jj < 6; jj++) {
            float uj = u[jc + jj];
            #pragma unroll
            for (int r = 0; r < 4; r++) {
                float lo = __uint_as_float((unsigned)(acc[r][jj] & 0xffffffffull)) + uj;
                float hi = __uint_as_float((unsigned)(acc[r][jj] >> 32)) + uj;
                sum6[jj] += lo + hi;
                sq6[jj]  += lo * lo + hi * hi;
            }
        }
    }
    #pragma unroll
    for (int jj = 0; jj < 6; jj++) {
        float s1 = sum6[jj], s2 = sq6[jj];
        #pragma unroll
        for (int off = 16; off > 0; off >>= 1) {
            s1 += __shfl_down_sync(0xffffffffu, s1, off);
            s2 += __shfl_down_sync(0xffffffffu, s2, off);
        }
        if (l == 0) {
            g_part[b * 72 + jc + jj]      = s1;
            g_part[b * 72 + 36 + jc + jj] = s2;
        }
    }

    // ---- stage h into smem (alias), then coalesced dump to global ----
    __syncthreads();   // all warps done reading histP/msp region? (msp not aliased; histP is)
    if (act) {
        #pragma unroll
        for (int jj = 0; jj < 6; jj++) {
            float uj = u[jc + jj];
            #pragma unroll
            for (int r = 0; r < 4; r++) {
                float lo = __uint_as_float((unsigned)(acc[r][jj] & 0xffffffffull)) + uj;
                float hi = __uint_as_float((unsigned)(acc[r][jj] >> 32)) + uj;
                int s0 = 8 * l + 2 * r;
                htile[s0 * 37 + jc + jj]       = lo;
                htile[(s0 + 1) * 37 + jc + jj] = hi;
            }
        }
    }
    __syncthreads();
    {
        float* dst = g_h + (size_t)b * ROWF;
        for (int g = tid; g < ROWF; g += 192) {
            int s = g / 36;
            dst[g] = htile[s * 37 + (g - s * 36)];
        }
    }
}

// ---------------- pass 2: reduce stat partials (deterministic) ------------
__global__ void __launch_bounds__(256)
reduce_stats_kernel()
{
    __shared__ float red[256];
    const int r   = blockIdx.x;      // 0..71
    const int tid = threadIdx.x;
    float s = 0.f;
    for (int b = tid; b < BB; b += 256) s += g_part[b * 72 + r];
    red[tid] = s;
    __syncthreads();
    #pragma unroll
    for (int o = 128; o > 0; o >>= 1) {
        if (tid < o) red[tid] += red[tid + o];
        __syncthreads();
    }
    if (tid == 0) g_stats[r] = red[0];
}

// ---------------- pass 3: BN + Dice + W2 + weighted pooling ---------------
__global__ void __launch_bounds__(256)
pass3_kernel(const float* __restrict__ hist,
             const float* __restrict__ gamma,
             const float* __restrict__ beta,
             const float* __restrict__ alpha,
             const float* __restrict__ W2,
             const float* __restrict__ b2,
             float* __restrict__ out)
{
    __shared__ float htile[SS * 37];
    __shared__ float wrow[SS];
    __shared__ float acoef[36], ccoef[36], w2s[36];
    __shared__ float pool[256];

    const int tid = threadIdx.x;
    const int b   = blockIdx.x;

    if (tid < 36) {
        float sm = g_stats[tid];
        float sq = g_stats[36 + tid];
        const float invN = 1.0f / (float)NROWS;
        float mu   = sm * invN;
        float var  = sq * invN - mu * mu;
        float rstd = rsqrtf(var + 1e-5f);
        float a    = gamma[tid] * rstd;
        acoef[tid] = a;
        ccoef[tid] = beta[tid] - mu * a;
        w2s[tid]   = W2[tid];
    }
    const float alph = alpha[0];
    const float b2v  = b2[0];

    // coalesced load of this batch's h tile
    {
        const float* src = g_h + (size_t)b * ROWF;
        for (int g = tid; g < ROWF; g += 256) {
            int s = g / 36;
            htile[s * 37 + (g - s * 36)] = src[g];
        }
    }
    __syncthreads();

    if (tid < SS) {
        const int s = tid;
        float hn[36];
        float mean = 0.f;
        #pragma unroll
        for (int j = 0; j < 36; j++) {
            float v = acoef[j] * htile[s * 37 + j] + ccoef[j];
            hn[j] = v;
            mean += v;
        }
        mean *= (1.0f / 36.0f);
        float var = 0.f;
        #pragma unroll
        for (int j = 0; j < 36; j++) {
            float d = hn[j] - mean;
            var += d * d;
        }
        var *= (1.0f / 36.0f);
        float rs = rsqrtf(var + 1e-3f);
        float wa = 0.f;
        #pragma unroll
        for (int j = 0; j < 36; j++) {
            float x  = (hn[j] - mean) * rs;
            float ps = 1.0f / (1.0f + __expf(-x));
            float hv = hn[j] * (ps + (1.0f - ps) * alph);
            wa += hv * w2s[j];
        }
        wrow[s] = wa + b2v;
    }
    __syncthreads();

    // weighted pooling: out[b][d] = sum_s wrow[s] * hist[b][s][d]
    const float* hb = hist + (size_t)b * (SS * DD);
    const int d = tid & 63;
    const int q = tid >> 6;            // 0..3
    float acc = 0.f;
    for (int s = q; s < SS; s += 4)
        acc += wrow[s] * hb[s * 64 + d];
    pool[tid] = acc;
    __syncthreads();
    if (tid < 64)
        out[b * 64 + tid] = pool[tid] + pool[64 + tid] + pool[128 + tid] + pool[192 + tid];
}

// ---------------- launch ----------------
extern "C" void kernel_launch(void* const* d_in, const int* in_sizes, int n_in,
                              void* d_out, int out_size)
{
    const float* history = (const float*)d_in[0];
    const float* cand    = (const float*)d_in[1];
    const float* W1      = (const float*)d_in[2];
    const float* b1      = (const float*)d_in[3];
    const float* gamma   = (const float*)d_in[4];
    const float* beta    = (const float*)d_in[5];
    const float* alpha   = (const float*)d_in[6];
    const float* W2      = (const float*)d_in[7];
    const float* b2      = (const float*)d_in[8];
    float* out = (float*)d_out;

    cudaFuncSetAttribute(pass1_kernel,
                         cudaFuncAttributeMaxDynamicSharedMemorySize, SMEM1);

    pass1_kernel<<<BB, 192, SMEM1>>>(history, cand, W1, b1);
    reduce_stats_kernel<<<72, 256>>>();
    pass3_kernel<<<BB, 256>>>(history, gamma, beta, alpha, W2, b2, out);
}

// round 3
// speedup vs baseline: 1.4415x; 1.4415x over previous
#include <cuda_runtime.h>
#include <cstdint>

// Problem constants
#define BB 4096
#define SS 200
#define DD 64
#define HH 36
#define NROWS (BB*SS)          // 819200
#define ROWF  (SS*HH)          // 7200 floats of h per batch

// ---------------- device scratch (no allocations allowed) ----------------
// h stored TRANSPOSED per batch: g_h[b*7200 + j*200 + s]
__device__ float g_h[(size_t)NROWS * HH];     // 118 MB staged h^T
__device__ float g_part[BB * 72];             // per-block [sum(36), sumsq(36)]
__device__ float g_stats[72];                 // reduced sums

// packed fp32x2 FMA (FFMA2) — double-rate fp32 on sm_103a.
// NOT volatile: let ptxas schedule freely.
__device__ __forceinline__ void ffma2(unsigned long long& d,
                                      unsigned long long a,
                                      unsigned long long b) {
    asm("fma.rn.f32x2 %0, %1, %2, %0;" : "+l"(d) : "l"(a), "l"(b));
}

// ---------------- pass 1: per-batch GEMM h = hist @ M_b + u_b -------------
// grid = 4096 blocks (1 batch each), 192 threads.
// Dynamic SMEM layout (stride padded to 210 floats = 105 u64 per k-row):
//   [0,53760)          float hp[64][210] : hp[k][2p+h] = hist[row 2p+h][k]
//   [53760,72192)      float2 msp[64][36]: splatted M, msp[k][j] = {M,M}
//   [72192,72336)      float u[36]
//   [72336,72592)      float cbuf[64]
#define HP_STRIDE_F 210
#define HP_STRIDE_U 105
#define MSP_OFF   53760
#define U_OFF     72192
#define CB_OFF    72336
#define SMEM1     72592

__global__ void __launch_bounds__(192, 3)
pass1_kernel(const float* __restrict__ hist,
             const float* __restrict__ cand,
             const float* __restrict__ W1,
             const float* __restrict__ b1)
{
    extern __shared__ unsigned char smem_raw[];
    float*  hpF   = (float*)smem_raw;
    const unsigned long long* hpU = (const unsigned long long*)smem_raw;
    float2* msp2  = (float2*)(smem_raw + MSP_OFF);
    float*  u     = (float*)(smem_raw + U_OFF);
    float*  cbuf  = (float*)(smem_raw + CB_OFF);

    const int tid = threadIdx.x;
    const int b   = blockIdx.x;
    const float* hb = hist + (size_t)b * (SS * DD);

    // stage candidate
    if (tid < 64) cbuf[tid] = cand[b * 64 + tid];
    __syncthreads();

    // build M splat pairs: M[k][j] = W1[64+k][j] - W1[128+k][j] + cand[k]*W1[192+k][j]
    for (int e = tid; e < 64 * 36; e += 192) {
        int k = e / 36;
        int j = e - k * 36;
        float m = W1[(64 + k) * 36 + j] - W1[(128 + k) * 36 + j]
                + cbuf[k] * W1[(192 + k) * 36 + j];
        msp2[e] = make_float2(m, m);
    }
    // build u[j] = b1[j] + sum_k cand[k]*(W1[k][j] + W1[128+k][j])
    if (tid < 36) {
        int j = tid;
        float a = b1[j];
        #pragma unroll 8
        for (int k = 0; k < 64; k++)
            a += cbuf[k] * (W1[k * 36 + j] + W1[(128 + k) * 36 + j]);
        u[j] = a;
    }
    // load hist tile, transposed: hp[k][s] = hist[s][k]
    // coalesced LDG (consecutive lanes = consecutive float4); STS 4-way max
    // conflict thanks to 210-float row stride (4*210 = 840 ≡ 8 mod 32).
    {
        const float4* h4 = (const float4*)hb;     // 200*64/4 = 3200 float4
        for (int f = tid; f < 3200; f += 192) {
            float4 v = h4[f];
            int s  = f >> 4;
            int d4 = (f & 15) << 2;
            hpF[(d4 + 0) * HP_STRIDE_F + s] = v.x;
            hpF[(d4 + 1) * HP_STRIDE_F + s] = v.y;
            hpF[(d4 + 2) * HP_STRIDE_F + s] = v.z;
            hpF[(d4 + 3) * HP_STRIDE_F + s] = v.w;
        }
    }
    __syncthreads();

    // ---- GEMM: warp w owns cols [6w,6w+6), lane l (<25) owns row-pairs
    //      p = i*25 + l (i=0..3), pair p = rows (2p, 2p+1) ----
    // Hist loads: 4x LDS.64 consecutive-lane => conflict-free.
    // M loads: 3x LDS.128 broadcast => 1 wavefront each.
    const int w  = tid >> 5;          // 0..5
    const int l  = tid & 31;          // 0..31 (25 active)
    const int jc = w * 6;
    const bool act = (l < 25);

    unsigned long long acc[4][6];
    #pragma unroll
    for (int r = 0; r < 4; r++)
        #pragma unroll
        for (int jj = 0; jj < 6; jj++) acc[r][jj] = 0ull;

    if (act) {
        const ulonglong2* mspV = (const ulonglong2*)(smem_raw + MSP_OFF);
        #pragma unroll 2
        for (int k = 0; k < 64; k++) {
            unsigned long long h0 = hpU[k * HP_STRIDE_U + l];
            unsigned long long h1 = hpU[k * HP_STRIDE_U + 25 + l];
            unsigned long long h2 = hpU[k * HP_STRIDE_U + 50 + l];
            unsigned long long h3 = hpU[k * HP_STRIDE_U + 75 + l];
            const ulonglong2* mp = mspV + (k * 18 + 3 * w);
            ulonglong2 m01 = mp[0];
            ulonglong2 m23 = mp[1];
            ulonglong2 m45 = mp[2];
            unsigned long long mm[6] = {m01.x, m01.y, m23.x, m23.y, m45.x, m45.y};
            #pragma unroll
            for (int jj = 0; jj < 6; jj++) {
                ffma2(acc[0][jj], h0, mm[jj]);
                ffma2(acc[1][jj], h1, mm[jj]);
                ffma2(acc[2][jj], h2, mm[jj]);
                ffma2(acc[3][jj], h3, mm[jj]);
            }
        }
    }

    // ---- per-thread stats + direct coalesced store of h^T ----
    float sum6[6], sq6[6];
    #pragma unroll
    for (int jj = 0; jj < 6; jj++) { sum6[jj] = 0.f; sq6[jj] = 0.f; }

    if (act) {
        float* dst = g_h + (size_t)b * ROWF;
        #pragma unroll
        for (int jj = 0; jj < 6; jj++) {
            float uj = u[jc + jj];
            #pragma unroll
            for (int i = 0; i < 4; i++) {
                float lo = __uint_as_float((unsigned)(acc[i][jj] & 0xffffffffull)) + uj;
                float hi = __uint_as_float((unsigned)(acc[i][jj] >> 32)) + uj;
                sum6[jj] += lo + hi;
                sq6[jj]  += lo * lo + hi * hi;
                // pair p = i*25 + l  ->  rows (2p, 2p+1), column jc+jj
                // float2 store: consecutive lanes -> consecutive 8B => coalesced
                *(float2*)(dst + (jc + jj) * SS + 2 * (i * 25 + l)) = make_float2(lo, hi);
            }
        }
    }
    #pragma unroll
    for (int jj = 0; jj < 6; jj++) {
        float s1 = sum6[jj], s2 = sq6[jj];
        #pragma unroll
        for (int off = 16; off > 0; off >>= 1) {
            s1 += __shfl_down_sync(0xffffffffu, s1, off);
            s2 += __shfl_down_sync(0xffffffffu, s2, off);
        }
        if (l == 0) {
            g_part[b * 72 + jc + jj]      = s1;
            g_part[b * 72 + 36 + jc + jj] = s2;
        }
    }
}

// ---------------- pass 2: reduce stat partials (deterministic) ------------
__global__ void __launch_bounds__(256)
reduce_stats_kernel()
{
    __shared__ float red[256];
    const int r   = blockIdx.x;      // 0..71
    const int tid = threadIdx.x;
    float s = 0.f;
    for (int b = tid; b < BB; b += 256) s += g_part[b * 72 + r];
    red[tid] = s;
    __syncthreads();
    #pragma unroll
    for (int o = 128; o > 0; o >>= 1) {
        if (tid < o) red[tid] += red[tid + o];
        __syncthreads();
    }
    if (tid == 0) g_stats[r] = red[0];
}

// ---------------- pass 3: BN + Dice + W2 + weighted pooling ---------------
// h^T layout makes all g_h reads fully coalesced; no smem tile needed.
__global__ void __launch_bounds__(256)
pass3_kernel(const float* __restrict__ hist,
             const float* __restrict__ gamma,
             const float* __restrict__ beta,
             const float* __restrict__ alpha,
             const float* __restrict__ W2,
             const float* __restrict__ b2,
             float* __restrict__ out)
{
    __shared__ float wrow[SS];
    __shared__ float acoef[36], ccoef[36], w2s[36];
    __shared__ float pool[256];

    const int tid = threadIdx.x;
    const int b   = blockIdx.x;

    if (tid < 36) {
        float sm = g_stats[tid];
        float sq = g_stats[36 + tid];
        const float invN = 1.0f / (float)NROWS;
        float mu   = sm * invN;
        float var  = sq * invN - mu * mu;
        float rstd = rsqrtf(var + 1e-5f);
        float a    = gamma[tid] * rstd;
        acoef[tid] = a;
        ccoef[tid] = beta[tid] - mu * a;
        w2s[tid]   = W2[tid];
    }
    const float alph = alpha[0];
    const float b2v  = b2[0];
    __syncthreads();

    if (tid < SS) {
        const int s = tid;
        const float* hT = g_h + (size_t)b * ROWF;  // [j][s]
        float hn[36];
        float mean = 0.f;
        #pragma unroll
        for (int j = 0; j < 36; j++) {
            float v = acoef[j] * __ldg(hT + j * SS + s) + ccoef[j];
            hn[j] = v;
            mean += v;
        }
        mean *= (1.0f / 36.0f);
        float var = 0.f;
        #pragma unroll
        for (int j = 0; j < 36; j++) {
            float d = hn[j] - mean;
            var += d * d;
        }
        var *= (1.0f / 36.0f);
        float rs = rsqrtf(var + 1e-3f);
        float wa = 0.f;
        #pragma unroll
        for (int j = 0; j < 36; j++) {
            float x  = (hn[j] - mean) * rs;
            float ps = 1.0f / (1.0f + __expf(-x));
            float hv = hn[j] * (ps + (1.0f - ps) * alph);
            wa += hv * w2s[j];
        }
        wrow[s] = wa + b2v;
    }
    __syncthreads();

    // weighted pooling: out[b][d] = sum_s wrow[s] * hist[b][s][d]
    const float* hb = hist + (size_t)b * (SS * DD);
    const int d = tid & 63;
    const int q = tid >> 6;            // 0..3
    float acc = 0.f;
    for (int s = q; s < SS; s += 4)
        acc += wrow[s] * hb[s * 64 + d];
    pool[tid] = acc;
    __syncthreads();
    if (tid < 64)
        out[b * 64 + tid] = pool[tid] + pool[64 + tid] + pool[128 + tid] + pool[192 + tid];
}

// ---------------- launch ----------------
extern "C" void kernel_launch(void* const* d_in, const int* in_sizes, int n_in,
                              void* d_out, int out_size)
{
    const float* history = (const float*)d_in[0];
    const float* cand    = (const float*)d_in[1];
    const float* W1      = (const float*)d_in[2];
    const float* b1      = (const float*)d_in[3];
    const float* gamma   = (const float*)d_in[4];
    const float* beta    = (const float*)d_in[5];
    const float* alpha   = (const float*)d_in[6];
    const float* W2      = (const float*)d_in[7];
    const float* b2      = (const float*)d_in[8];
    float* out = (float*)d_out;

    cudaFuncSetAttribute(pass1_kernel,
                         cudaFuncAttributeMaxDynamicSharedMemorySize, SMEM1);

    pass1_kernel<<<BB, 192, SMEM1>>>(history, cand, W1, b1);
    reduce_stats_kernel<<<72, 256>>>();
    pass3_kernel<<<BB, 256>>>(history, gamma, beta, alpha, W2, b2, out);
}